// round 16
// baseline (speedup 1.0000x reference)
#include <cuda_runtime.h>
#include <cuda_fp16.h>
#include <cstdint>

#define FDIM 128
#define HDIM 256
#define E_EDGES 262144
#define T_TRIP 393216
#define NPAD 20096
#define TABN 4096
#define TROWS 4097
#define TOFF ((size_t)TROWS * 256)

// CTA 128x128: A fp16 2-limb (2x16KB) + B fp16 1-limb (16KB) per 64-K chunk
#define SA_HI 0
#define SA_MID (16 * 1024)
#define SB (32 * 1024)
#define STAGE_BYTES (48 * 1024)
#define SMEM_GEMM (2 * STAGE_BYTES)

__device__ __half g_x_hi[(size_t)T_TRIP * HDIM];
__device__ __half g_x_mid[(size_t)T_TRIP * HDIM];
__device__ __half g_y_hi[(size_t)T_TRIP * HDIM];
__device__ __half g_y_mid[(size_t)T_TRIP * HDIM];
__device__ __half g_h_hi[(size_t)NPAD * FDIM];
__device__ __half g_h_mid[(size_t)NPAD * FDIM];
__device__ float g_P[5ull * NPAD * HDIM];
__device__ float g_T[3 * TOFF];
__device__ float g_scr[(size_t)T_TRIP * 6];
#define PSZ ((size_t)NPAD * HDIM)
#define E0A 0
#define E0B 32768
#define E1 98304
#define E2 163840
#define T0A 229376
#define T0B 262144
#define T0C 294912
#define T1 393216
#define T2 458752
__device__ __half g_w[524288];

__device__ __forceinline__ uint32_t smem_u32(const void* p) {
    uint32_t a;
    asm("{ .reg .u64 t; cvta.to.shared.u64 t, %1; cvt.u32.u64 %0, t; }" : "=r"(a) : "l"(p));
    return a;
}
__device__ __forceinline__ void cp16(uint32_t d, const void* s) {
    asm volatile("cp.async.cg.shared.global [%0], [%1], 16;" :: "r"(d), "l"(s));
}
#define CP_COMMIT() asm volatile("cp.async.commit_group;" ::: "memory")
#define CP_WAIT0() asm volatile("cp.async.wait_group 0;" ::: "memory")
#define CP_WAIT1() asm volatile("cp.async.wait_group 1;" ::: "memory")
#define LDSM4(r0, r1, r2, r3, a) \
    asm volatile("ldmatrix.sync.aligned.m8n8.x4.shared.b16 {%0,%1,%2,%3}, [%4];" \
                 : "=r"(r0), "=r"(r1), "=r"(r2), "=r"(r3) : "r"(a))

__device__ __forceinline__ void mma_f16(float c[4], const uint32_t a[4], const uint32_t b[2]) {
    asm volatile(
        "mma.sync.aligned.m16n8k16.row.col.f32.f16.f16.f32 "
        "{%0,%1,%2,%3}, {%4,%5,%6,%7}, {%8,%9}, {%0,%1,%2,%3};"
        : "+f"(c[0]), "+f"(c[1]), "+f"(c[2]), "+f"(c[3])
        : "r"(a[0]), "r"(a[1]), "r"(a[2]), "r"(a[3]), "r"(b[0]), "r"(b[1]));
}
__device__ __forceinline__ float silu_f(float x) { return x / (1.0f + __expf(-x)); }
__device__ __forceinline__ uint32_t pkhf2(__half a, __half b) {
    __half2 v(a, b);
    return *reinterpret_cast<uint32_t*>(&v);
}
__device__ __forceinline__ void silu_split2(float v0, float v1, uint32_t* oh, uint32_t* om) {
    float a0 = silu_f(v0), a1 = silu_f(v1);
    __half h0 = __float2half_rn(a0), h1 = __float2half_rn(a1);
    *oh = pkhf2(h0, h1);
    *om = pkhf2(__float2half_rn(a0 - __half2float(h0)),
                __float2half_rn(a1 - __half2float(h1)));
}

struct Frag {
    int a_row, a_kh, b_row, b_kh;
};
__device__ __forceinline__ void mma_chunk(uint32_t stage, int wm, int wn, const Frag& f,
                                          float acc[2][8][4]) {
#pragma unroll
    for (int ks = 0; ks < 4; ks++) {
        uint32_t aHf[2][4], aMf[2][4], bF[8][2];
#pragma unroll
        for (int mt = 0; mt < 2; mt++) {
            int r = wm + mt * 16 + f.a_row;
            uint32_t off = r * 128 + (((ks * 2 + f.a_kh) ^ (r & 7)) << 4);
            LDSM4(aHf[mt][0], aHf[mt][1], aHf[mt][2], aHf[mt][3], stage + SA_HI + off);
            LDSM4(aMf[mt][0], aMf[mt][1], aMf[mt][2], aMf[mt][3], stage + SA_MID + off);
        }
#pragma unroll
        for (int np = 0; np < 4; np++) {
            int r = wn + np * 16 + f.b_row;
            uint32_t off = r * 128 + (((ks * 2 + f.b_kh) ^ (r & 7)) << 4);
            uint32_t r0, r1, r2, r3;
            LDSM4(r0, r1, r2, r3, stage + SB + off);
            bF[np * 2][0] = r0; bF[np * 2][1] = r1;
            bF[np * 2 + 1][0] = r2; bF[np * 2 + 1][1] = r3;
        }
#pragma unroll
        for (int mt = 0; mt < 2; mt++)
#pragma unroll
            for (int nt = 0; nt < 8; nt++) {
                mma_f16(acc[mt][nt], aHf[mt], bF[nt]);
                mma_f16(acc[mt][nt], aMf[mt], bF[nt]);
            }
    }
}

__device__ __forceinline__ void load_chunk(uint32_t stage, int t, size_t koff,
                                           const char* aH, const char* aM,
                                           const char* bW, size_t ldb) {
#pragma unroll
    for (int i = 0; i < 4; i++) {
        int idx = t + i * 256;
        int r = idx >> 3, c16 = idx & 7;
        uint32_t doff = r * 128 + ((c16 ^ (r & 7)) << 4);
        size_t soff = (size_t)r * ldb + koff + c16 * 16;
        cp16(stage + SA_HI + doff, aH + soff);
        cp16(stage + SA_MID + doff, aM + soff);
        cp16(stage + SB + doff, bW + soff);
    }
    CP_COMMIT();
}

// EPI: 0 = silu+fp16 limb split, 1 = raw f32, 2 = fused out-layer (W3 partials)
// Proven 2-stage pattern: load(c+1); WAIT; sync (visibility); mma(c); sync (reuse).
template <int EPI, int NC>
__device__ __forceinline__ void gemm_core(
    const __half* Ahi, const __half* Amid, const __half* Bw,
    int ld, void* C1, void* C2, const float* W3,
    int row0, int n0cta, int cblk, char* smem) {
    uint32_t sb = smem_u32(smem);
    int t = threadIdx.x, lane = t & 31, w = t >> 5;
    int wm = (w & 3) * 32, wn = (w >> 2) * 64;

    const char* aH = (const char*)(Ahi + (size_t)row0 * ld);
    const char* aM = (const char*)(Amid + (size_t)row0 * ld);
    const char* bW = (const char*)(Bw + (size_t)n0cta * ld);
    const size_t ldb = (size_t)ld * 2;

    float acc[2][8][4];
#pragma unroll
    for (int i = 0; i < 2; i++)
#pragma unroll
        for (int j = 0; j < 8; j++)
#pragma unroll
            for (int q = 0; q < 4; q++) acc[i][j][q] = 0.0f;
    Frag f{lane & 15, lane >> 4, (lane & 7) + ((lane >> 4) << 3), (lane >> 3) & 1};

    load_chunk(sb, t, 0, aH, aM, bW, ldb);
#pragma unroll
    for (int c = 0; c < NC; c++) {
        if (c + 1 < NC) {
            load_chunk(sb + ((c + 1) & 1) * STAGE_BYTES, t, (size_t)(c + 1) * 128,
                       aH, aM, bW, ldb);
            CP_WAIT1();
        } else {
            CP_WAIT0();
        }
        __syncthreads();
        mma_chunk(sb + (c & 1) * STAGE_BYTES, wm, wn, f, acc);
        __syncthreads();
    }

    int mrow = lane >> 2, ncol = (lane & 3) * 2;
    if (EPI == 2) {
        float* w3s = (float*)smem;
        float* rsum = (float*)smem + 384;
        for (int i = t; i < 384; i += 256) w3s[i] = W3[n0cta * 3 + i];
        for (int i = t; i < 384; i += 256) rsum[i] = 0.0f;
        __syncthreads();
        float part[4][3];
#pragma unroll
        for (int rs = 0; rs < 4; rs++)
#pragma unroll
            for (int o = 0; o < 3; o++) part[rs][o] = 0.0f;
#pragma unroll
        for (int mt = 0; mt < 2; mt++)
#pragma unroll
            for (int nt = 0; nt < 8; nt++)
#pragma unroll
                for (int sr = 0; sr < 2; sr++)
#pragma unroll
                    for (int e = 0; e < 2; e++) {
                        int cl = wn + nt * 8 + ncol + e;
                        float v = silu_f(acc[mt][nt][sr * 2 + e]);
#pragma unroll
                        for (int o = 0; o < 3; o++)
                            part[mt * 2 + sr][o] = fmaf(v, w3s[cl * 3 + o], part[mt * 2 + sr][o]);
                    }
#pragma unroll
        for (int rs = 0; rs < 4; rs++)
#pragma unroll
            for (int o = 0; o < 3; o++) {
                part[rs][o] += __shfl_xor_sync(0xffffffffu, part[rs][o], 1);
                part[rs][o] += __shfl_xor_sync(0xffffffffu, part[rs][o], 2);
            }
        if ((w >> 2) == 0 && (lane & 3) == 0) {
#pragma unroll
            for (int rs = 0; rs < 4; rs++) {
                int r = wm + (rs >> 1) * 16 + (rs & 1) * 8 + mrow;
#pragma unroll
                for (int o = 0; o < 3; o++) rsum[r * 3 + o] = part[rs][o];
            }
        }
        __syncthreads();
        if ((w >> 2) == 1 && (lane & 3) == 0) {
#pragma unroll
            for (int rs = 0; rs < 4; rs++) {
                int r = wm + (rs >> 1) * 16 + (rs & 1) * 8 + mrow;
#pragma unroll
                for (int o = 0; o < 3; o++) rsum[r * 3 + o] += part[rs][o];
            }
        }
        __syncthreads();
        float* scr = (float*)C1;
        for (int i = t; i < 384; i += 256) {
            int r = i / 3, o = i % 3;
            scr[((size_t)(row0 + r) * 2 + cblk) * 3 + o] = rsum[i];
        }
        return;
    }
#pragma unroll
    for (int mt = 0; mt < 2; mt++)
#pragma unroll
        for (int nt = 0; nt < 8; nt++) {
            int r = row0 + wm + mt * 16 + mrow;
            int cc = n0cta + wn + nt * 8 + ncol;
            if (EPI == 0) {
                uint32_t oh, om;
                silu_split2(acc[mt][nt][0], acc[mt][nt][1], &oh, &om);
                *(uint32_t*)((__half*)C1 + (size_t)r * HDIM + cc) = oh;
                *(uint32_t*)((__half*)C2 + (size_t)r * HDIM + cc) = om;
                silu_split2(acc[mt][nt][2], acc[mt][nt][3], &oh, &om);
                *(uint32_t*)((__half*)C1 + (size_t)(r + 8) * HDIM + cc) = oh;
                *(uint32_t*)((__half*)C2 + (size_t)(r + 8) * HDIM + cc) = om;
            } else {
                *(float2*)((float*)C1 + (size_t)r * HDIM + cc) =
                    make_float2(acc[mt][nt][0], acc[mt][nt][1]);
                *(float2*)((float*)C1 + (size_t)(r + 8) * HDIM + cc) =
                    make_float2(acc[mt][nt][2], acc[mt][nt][3]);
            }
        }
}

template <int EPI, int NC>
__global__ void __launch_bounds__(256, 2) gemm_kernel(
    const __half* __restrict__ Ahi, const __half* __restrict__ Amid,
    const __half* __restrict__ Bw,
    int ld, void* __restrict__ C1, void* __restrict__ C2,
    const float* __restrict__ W3) {
    extern __shared__ char smem[];
    gemm_core<EPI, NC>(Ahi, Amid, Bw, ld, C1, C2, W3,
                       blockIdx.y * 128, blockIdx.x * 128, blockIdx.x, smem);
}

struct PG {
    int boff[5];
    size_t coff[5];
};
__global__ void __launch_bounds__(256, 2) pgemm_kernel(
    const __half* __restrict__ hH, const __half* __restrict__ hM,
    const __half* __restrict__ wW, float* __restrict__ P, PG pg) {
    extern __shared__ char smem[];
    int z = blockIdx.z;
    gemm_core<1, 2>(hH, hM, wW + pg.boff[z], 128,
                    P + pg.coff[z], nullptr, nullptr,
                    blockIdx.y * 128, blockIdx.x * 128, blockIdx.x, smem);
}

__global__ void prep_h_kernel(const float* __restrict__ h,
                              __half* __restrict__ hi, __half* __restrict__ mid) {
    size_t idx = (size_t)blockIdx.x * 256 + threadIdx.x;
    int row = (int)(idx >> 7);
    float v = (row < 20000) ? h[idx] : 0.0f;
    __half hh = __float2half_rn(v);
    hi[idx] = hh;
    mid[idx] = __float2half_rn(v - __half2float(hh));
}

struct WS {
    const float* src[9];
    int KP[9], off[9];
};
__global__ void prep_w_kernel(WS S, __half* __restrict__ w) {
    int z = blockIdx.z;
    int KP = S.KP[z];
    if (blockIdx.x >= KP) return;
    int idx = blockIdx.x * 256 + threadIdx.x;
    int n = idx / KP, k = idx % KP;
    w[S.off[z] + idx] = __float2half_rn(S.src[z][(size_t)k * HDIM + n]);
}

__global__ void table_kernel(const float* __restrict__ eW0, const float* __restrict__ tW0,
                             const float* __restrict__ mu) {
    __shared__ float Wsm[100 * 64];
    __shared__ float rbf[32 * 100];
    int z = blockIdx.z, cb = blockIdx.y, r0 = blockIdx.x * 32;
    const float* Wsrc = ((z == 0) ? eW0 + 65536 : ((z == 1) ? tW0 + 98304 : tW0 + 123904))
                        + cb * 64;
    float* Tout = g_T + (size_t)z * TOFF + cb * 64;
    int t = threadIdx.x;
    for (int i = t; i < 6400; i += 256) {
        int k = i >> 6, c = i & 63;
        Wsm[i] = Wsrc[k * 256 + c];
    }
    for (int i = t; i < 3200; i += 256) {
        int rr = i / 100, k = i % 100;
        float r = (float)(r0 + rr) * (10.0f / (float)TABN);
        float d = __ldg(mu + k) - r;
        rbf[i] = expf(-10.0f * d * d);
    }
    __syncthreads();
    int col = t & 63, rl = t >> 6;
    float acc[8];
#pragma unroll
    for (int p = 0; p < 8; p++) acc[p] = 0.0f;
#pragma unroll 4
    for (int k = 0; k < 100; k++) {
        float wv = Wsm[k * 64 + col];
#pragma unroll
        for (int p = 0; p < 8; p++)
            acc[p] = fmaf(rbf[(rl + p * 4) * 100 + k], wv, acc[p]);
    }
#pragma unroll
    for (int p = 0; p < 8; p++) {
        int row = r0 + rl + p * 4;
        if (row <= TABN) Tout[(size_t)row * 256 + col] = acc[p];
    }
}

template <int MODE>
__global__ void __launch_bounds__(512) l0g_kernel(
    const float* __restrict__ rA, const float* __restrict__ rB,
    const float* __restrict__ cosv, const float* __restrict__ sinv,
    const int* __restrict__ iA, const int* __restrict__ iB, const int* __restrict__ iC,
    const float* __restrict__ Ta, const float* __restrict__ Tb,
    const float* __restrict__ Wcs,
    const float* __restrict__ Pa, const float* __restrict__ Pb, const float* __restrict__ Pc,
    __half* __restrict__ Chi, __half* __restrict__ Cmid) {
    int w = threadIdx.x >> 5, lane = threadIdx.x & 31;
    int row = blockIdx.x * 16 + w;

    float ua = rA[row] * ((float)TABN / 10.0f);
    int ia = min((int)ua, TABN - 1);
    float fa = ua - (float)ia;
    const float4* t0 = (const float4*)(Ta + (size_t)ia * 256);
    const float4* pa = (const float4*)(Pa + (size_t)iA[row] * HDIM);
    const float4* pb = (const float4*)(Pb + (size_t)iB[row] * HDIM);

    const float4* u0 = nullptr;
    const float4* pc = nullptr;
    float fb = 0.0f, cv = 0.0f, sv = 0.0f;
    if (MODE) {
        float ub = rB[row] * ((float)TABN / 10.0f);
        int ib = min((int)ub, TABN - 1);
        fb = ub - (float)ib;
        u0 = (const float4*)(Tb + (size_t)ib * 256);
        pc = (const float4*)(Pc + (size_t)iC[row] * HDIM);
        cv = cosv[row];
        sv = sinv[row];
    }

#pragma unroll
    for (int g = 0; g < 2; g++) {
        int c4 = lane + g * 32;
        float4 a0 = t0[c4], a1 = t0[c4 + 64];
        float4 A = pa[c4], B = pb[c4];
        float v[4];
        v[0] = a0.x + fa * (a1.x - a0.x) + A.x + B.x;
        v[1] = a0.y + fa * (a1.y - a0.y) + A.y + B.y;
        v[2] = a0.z + fa * (a1.z - a0.z) + A.z + B.z;
        v[3] = a0.w + fa * (a1.w - a0.w) + A.w + B.w;
        if (MODE) {
            float4 b0 = u0[c4], b1 = u0[c4 + 64];
            float4 C = pc[c4];
            float4 wc = ((const float4*)Wcs)[c4];
            float4 ws = ((const float4*)(Wcs + 256))[c4];
            v[0] += b0.x + fb * (b1.x - b0.x) + C.x + cv * wc.x + sv * ws.x;
            v[1] += b0.y + fb * (b1.y - b0.y) + C.y + cv * wc.y + sv * ws.y;
            v[2] += b0.z + fb * (b1.z - b0.z) + C.z + cv * wc.z + sv * ws.z;
            v[3] += b0.w + fb * (b1.w - b0.w) + C.w + cv * wc.w + sv * ws.w;
        }
        uint2 oh, om;
        silu_split2(v[0], v[1], &oh.x, &om.x);
        silu_split2(v[2], v[3], &oh.y, &om.y);
        *(uint2*)(Chi + (size_t)row * HDIM + c4 * 4) = oh;
        *(uint2*)(Cmid + (size_t)row * HDIM + c4 * 4) = om;
    }
}

__global__ void sum_kernel(const float* __restrict__ scr, const float* __restrict__ b3,
                           float* __restrict__ out, int n3) {
    int i = blockIdx.x * 256 + threadIdx.x;
    if (i >= n3) return;
    int row = i / 3, o = i % 3;
    out[i] = scr[row * 6 + o] + scr[row * 6 + 3 + o] + b3[o];
}

extern "C" void kernel_launch(void* const* d_in, const int* in_sizes, int n_in,
                              void* d_out, int out_size) {
    const float* h = (const float*)d_in[0];
    const int* src = (const int*)d_in[1];
    const int* dst = (const int*)d_in[2];
    const float* enorm = (const float*)d_in[3];
    const int* tsrc = (const int*)d_in[4];
    const int* tdi = (const int*)d_in[5];
    const int* tdj = (const int*)d_in[6];
    const float* nij = (const float*)d_in[7];
    const float* nik = (const float*)d_in[8];
    const float* cosv = (const float*)d_in[9];
    const float* sinv = (const float*)d_in[10];
    const float* mu = (const float*)d_in[11];
    const float* eW0 = (const float*)d_in[12];
    const float* eW1 = (const float*)d_in[13];
    const float* eW2 = (const float*)d_in[14];
    const float* eW3 = (const float*)d_in[15];
    const float* eb3 = (const float*)d_in[16];
    const float* tW0 = (const float*)d_in[17];
    const float* tW1 = (const float*)d_in[18];
    const float* tW2 = (const float*)d_in[19];
    const float* tW3 = (const float*)d_in[20];
    const float* tb3 = (const float*)d_in[21];
    float* out = (float*)d_out;

    __half *xH, *xM, *yH, *yM, *hH, *hM, *wW;
    float *P, *T, *scr;
    cudaGetSymbolAddress((void**)&xH, g_x_hi);
    cudaGetSymbolAddress((void**)&xM, g_x_mid);
    cudaGetSymbolAddress((void**)&yH, g_y_hi);
    cudaGetSymbolAddress((void**)&yM, g_y_mid);
    cudaGetSymbolAddress((void**)&hH, g_h_hi);
    cudaGetSymbolAddress((void**)&hM, g_h_mid);
    cudaGetSymbolAddress((void**)&wW, g_w);
    cudaGetSymbolAddress((void**)&P, g_P);
    cudaGetSymbolAddress((void**)&T, g_T);
    cudaGetSymbolAddress((void**)&scr, g_scr);

    cudaFuncSetAttribute((const void*)gemm_kernel<0, 4>,
                         cudaFuncAttributeMaxDynamicSharedMemorySize, SMEM_GEMM);
    cudaFuncSetAttribute((const void*)gemm_kernel<2, 4>,
                         cudaFuncAttributeMaxDynamicSharedMemorySize, SMEM_GEMM);
    cudaFuncSetAttribute((const void*)pgemm_kernel,
                         cudaFuncAttributeMaxDynamicSharedMemorySize, SMEM_GEMM);

    WS S;
    const float* srcs[9] = {eW0, eW0 + 32768, eW1, eW2, tW0, tW0 + 32768, tW0 + 65536, tW1, tW2};
    int KPs[9] = {128, 128, 256, 256, 128, 128, 128, 256, 256};
    int offs[9] = {E0A, E0B, E1, E2, T0A, T0B, T0C, T1, T2};
    for (int i = 0; i < 9; i++) { S.src[i] = srcs[i]; S.KP[i] = KPs[i]; S.off[i] = offs[i]; }
    prep_w_kernel<<<dim3(256, 1, 9), 256>>>(S, wW);
    prep_h_kernel<<<(NPAD * FDIM) / 256, 256>>>(h, hH, hM);
    table_kernel<<<dim3((TROWS + 31) / 32, 4, 3), 256>>>(eW0, tW0, mu);
    PG pg;
    int boffs[5] = {E0A, E0B, T0A, T0B, T0C};
    for (int i = 0; i < 5; i++) { pg.boff[i] = boffs[i]; pg.coff[i] = (size_t)i * PSZ; }
    pgemm_kernel<<<dim3(2, NPAD / 128, 5), 256, SMEM_GEMM>>>(hH, hM, wW, P, pg);

    float *Pea = P, *Peb = P + PSZ, *Pta = P + 2 * PSZ, *Ptb = P + 3 * PSZ, *Ptc = P + 4 * PSZ;
    dim3 ge(2, E_EDGES / 128), gt(2, T_TRIP / 128);
    l0g_kernel<0><<<E_EDGES / 16, 512>>>(enorm, nullptr, nullptr, nullptr,
                                         src, dst, nullptr, T, nullptr, nullptr,
                                         Pea, Peb, nullptr, xH, xM);
    gemm_kernel<0, 4><<<ge, 256, SMEM_GEMM>>>(xH, xM, wW + E1, 256, yH, yM, nullptr);
    gemm_kernel<2, 4><<<ge, 256, SMEM_GEMM>>>(yH, yM, wW + E2, 256, scr, nullptr, eW3);
    sum_kernel<<<(E_EDGES * 3 + 255) / 256, 256>>>(scr, eb3, out, E_EDGES * 3);
    l0g_kernel<1><<<T_TRIP / 16, 512>>>(nij, nik, cosv, sinv,
                                        tsrc, tdi, tdj, T + TOFF, T + 2 * TOFF,
                                        tW0 + 149504, Pta, Ptb, Ptc, xH, xM);
    gemm_kernel<0, 4><<<gt, 256, SMEM_GEMM>>>(xH, xM, wW + T1, 256, yH, yM, nullptr);
    gemm_kernel<2, 4><<<gt, 256, SMEM_GEMM>>>(yH, yM, wW + T2, 256, scr, nullptr, tW3);
    sum_kernel<<<(T_TRIP * 3 + 255) / 256, 256>>>(scr, tb3, out + (size_t)E_EDGES * 3,
                                                  T_TRIP * 3);
}

// round 17
// speedup vs baseline: 1.0443x; 1.0443x over previous
#include <cuda_runtime.h>
#include <cuda_fp16.h>
#include <cstdint>

#define FDIM 128
#define HDIM 256
#define E_EDGES 262144
#define T_TRIP 393216
#define NPAD 20096
#define TABN 4096
#define TROWS 4097
#define TOFF ((size_t)TROWS * 256)

// CTA 128x128: A fp16 2-limb (2x16KB) + B fp16 1-limb (16KB) per 64-K chunk
#define SA_HI 0
#define SA_MID (16 * 1024)
#define SB (32 * 1024)
#define STAGE_BYTES (48 * 1024)
#define SMEM_GEMM (2 * STAGE_BYTES)

__device__ __half g_x_hi[(size_t)T_TRIP * HDIM];
__device__ __half g_x_mid[(size_t)T_TRIP * HDIM];
__device__ __half g_y_hi[(size_t)T_TRIP * HDIM];
__device__ __half g_y_mid[(size_t)T_TRIP * HDIM];
__device__ __half g_h_hi[(size_t)NPAD * FDIM];
__device__ __half g_h_mid[(size_t)NPAD * FDIM];
__device__ float g_P[5ull * NPAD * HDIM];
__device__ float g_T[3 * TOFF];
__device__ float g_scr[(size_t)T_TRIP * 6];
#define PSZ ((size_t)NPAD * HDIM)
#define E0A 0
#define E0B 32768
#define E1 98304
#define E2 163840
#define T0A 229376
#define T0B 262144
#define T0C 294912
#define T1 393216
#define T2 458752
__device__ __half g_w[524288];

__device__ __forceinline__ uint32_t smem_u32(const void* p) {
    uint32_t a;
    asm("{ .reg .u64 t; cvta.to.shared.u64 t, %1; cvt.u32.u64 %0, t; }" : "=r"(a) : "l"(p));
    return a;
}
__device__ __forceinline__ void cp16(uint32_t d, const void* s) {
    asm volatile("cp.async.cg.shared.global [%0], [%1], 16;" :: "r"(d), "l"(s));
}
#define CP_COMMIT() asm volatile("cp.async.commit_group;" ::: "memory")
#define CP_WAIT0() asm volatile("cp.async.wait_group 0;" ::: "memory")
#define LDSM4(r0, r1, r2, r3, a) \
    asm volatile("ldmatrix.sync.aligned.m8n8.x4.shared.b16 {%0,%1,%2,%3}, [%4];" \
                 : "=r"(r0), "=r"(r1), "=r"(r2), "=r"(r3) : "r"(a))

__device__ __forceinline__ void mma_f16(float c[4], const uint32_t a[4], const uint32_t b[2]) {
    asm volatile(
        "mma.sync.aligned.m16n8k16.row.col.f32.f16.f16.f32 "
        "{%0,%1,%2,%3}, {%4,%5,%6,%7}, {%8,%9}, {%0,%1,%2,%3};"
        : "+f"(c[0]), "+f"(c[1]), "+f"(c[2]), "+f"(c[3])
        : "r"(a[0]), "r"(a[1]), "r"(a[2]), "r"(a[3]), "r"(b[0]), "r"(b[1]));
}
__device__ __forceinline__ float silu_f(float x) { return x / (1.0f + __expf(-x)); }
__device__ __forceinline__ uint32_t pkhf2(__half a, __half b) {
    __half2 v(a, b);
    return *reinterpret_cast<uint32_t*>(&v);
}
__device__ __forceinline__ void silu_split2(float v0, float v1, uint32_t* oh, uint32_t* om) {
    float a0 = silu_f(v0), a1 = silu_f(v1);
    __half h0 = __float2half_rn(a0), h1 = __float2half_rn(a1);
    *oh = pkhf2(h0, h1);
    *om = pkhf2(__float2half_rn(a0 - __half2float(h0)),
                __float2half_rn(a1 - __half2float(h1)));
}

struct Frag {
    int a_row, a_kh, b_row, b_kh;
};
__device__ __forceinline__ void mma_chunk(uint32_t stage, int wm, int wn, const Frag& f,
                                          float acc[2][8][4]) {
#pragma unroll
    for (int ks = 0; ks < 4; ks++) {
        uint32_t aHf[2][4], aMf[2][4], bF[8][2];
#pragma unroll
        for (int mt = 0; mt < 2; mt++) {
            int r = wm + mt * 16 + f.a_row;
            uint32_t off = r * 128 + (((ks * 2 + f.a_kh) ^ (r & 7)) << 4);
            LDSM4(aHf[mt][0], aHf[mt][1], aHf[mt][2], aHf[mt][3], stage + SA_HI + off);
            LDSM4(aMf[mt][0], aMf[mt][1], aMf[mt][2], aMf[mt][3], stage + SA_MID + off);
        }
#pragma unroll
        for (int np = 0; np < 4; np++) {
            int r = wn + np * 16 + f.b_row;
            uint32_t off = r * 128 + (((ks * 2 + f.b_kh) ^ (r & 7)) << 4);
            uint32_t r0, r1, r2, r3;
            LDSM4(r0, r1, r2, r3, stage + SB + off);
            bF[np * 2][0] = r0; bF[np * 2][1] = r1;
            bF[np * 2 + 1][0] = r2; bF[np * 2 + 1][1] = r3;
        }
#pragma unroll
        for (int mt = 0; mt < 2; mt++)
#pragma unroll
            for (int nt = 0; nt < 8; nt++) {
                mma_f16(acc[mt][nt], aHf[mt], bF[nt]);
                mma_f16(acc[mt][nt], aMf[mt], bF[nt]);
            }
    }
}

__device__ __forceinline__ void load_chunk(uint32_t stage, int t, size_t koff,
                                           const char* aH, const char* aM,
                                           const char* bW, size_t ldb) {
#pragma unroll
    for (int i = 0; i < 4; i++) {
        int idx = t + i * 256;
        int r = idx >> 3, c16 = idx & 7;
        uint32_t doff = r * 128 + ((c16 ^ (r & 7)) << 4);
        size_t soff = (size_t)r * ldb + koff + c16 * 16;
        cp16(stage + SA_HI + doff, aH + soff);
        cp16(stage + SA_MID + doff, aM + soff);
        cp16(stage + SB + doff, bW + soff);
    }
    CP_COMMIT();
}

// EPI: 0 = silu+fp16 limb split, 1 = raw f32, 2 = fused out-layer (W3 partials)
// Single-sync 2-stage (CUTLASS order): WAIT(stage c) -> SYNC (visibility +
// frees slot (c-1)&1) -> issue load(c+1) into that slot -> MMA(c).
template <int EPI, int NC>
__device__ __forceinline__ void gemm_core(
    const __half* Ahi, const __half* Amid, const __half* Bw,
    int ld, void* C1, void* C2, const float* W3,
    int row0, int n0cta, int cblk, char* smem) {
    uint32_t sb = smem_u32(smem);
    int t = threadIdx.x, lane = t & 31, w = t >> 5;
    int wm = (w & 3) * 32, wn = (w >> 2) * 64;

    const char* aH = (const char*)(Ahi + (size_t)row0 * ld);
    const char* aM = (const char*)(Amid + (size_t)row0 * ld);
    const char* bW = (const char*)(Bw + (size_t)n0cta * ld);
    const size_t ldb = (size_t)ld * 2;

    float acc[2][8][4];
#pragma unroll
    for (int i = 0; i < 2; i++)
#pragma unroll
        for (int j = 0; j < 8; j++)
#pragma unroll
            for (int q = 0; q < 4; q++) acc[i][j][q] = 0.0f;
    Frag f{lane & 15, lane >> 4, (lane & 7) + ((lane >> 4) << 3), (lane >> 3) & 1};

    load_chunk(sb, t, 0, aH, aM, bW, ldb);
#pragma unroll
    for (int c = 0; c < NC; c++) {
        CP_WAIT0();      // this thread's stage-c copies done (only group pending)
        __syncthreads(); // publish stage c; all warps done with mma(c-1)
        if (c + 1 < NC)
            load_chunk(sb + ((c + 1) & 1) * STAGE_BYTES, t, (size_t)(c + 1) * 128,
                       aH, aM, bW, ldb);
        mma_chunk(sb + (c & 1) * STAGE_BYTES, wm, wn, f, acc);
    }
    __syncthreads();  // protect smem reuse by epilogue (EPI==2)

    int mrow = lane >> 2, ncol = (lane & 3) * 2;
    if (EPI == 2) {
        float* w3s = (float*)smem;
        float* rsum = (float*)smem + 384;
        for (int i = t; i < 384; i += 256) w3s[i] = W3[n0cta * 3 + i];
        for (int i = t; i < 384; i += 256) rsum[i] = 0.0f;
        __syncthreads();
        float part[4][3];
#pragma unroll
        for (int rs = 0; rs < 4; rs++)
#pragma unroll
            for (int o = 0; o < 3; o++) part[rs][o] = 0.0f;
#pragma unroll
        for (int mt = 0; mt < 2; mt++)
#pragma unroll
            for (int nt = 0; nt < 8; nt++)
#pragma unroll
                for (int sr = 0; sr < 2; sr++)
#pragma unroll
                    for (int e = 0; e < 2; e++) {
                        int cl = wn + nt * 8 + ncol + e;
                        float v = silu_f(acc[mt][nt][sr * 2 + e]);
#pragma unroll
                        for (int o = 0; o < 3; o++)
                            part[mt * 2 + sr][o] = fmaf(v, w3s[cl * 3 + o], part[mt * 2 + sr][o]);
                    }
#pragma unroll
        for (int rs = 0; rs < 4; rs++)
#pragma unroll
            for (int o = 0; o < 3; o++) {
                part[rs][o] += __shfl_xor_sync(0xffffffffu, part[rs][o], 1);
                part[rs][o] += __shfl_xor_sync(0xffffffffu, part[rs][o], 2);
            }
        if ((w >> 2) == 0 && (lane & 3) == 0) {
#pragma unroll
            for (int rs = 0; rs < 4; rs++) {
                int r = wm + (rs >> 1) * 16 + (rs & 1) * 8 + mrow;
#pragma unroll
                for (int o = 0; o < 3; o++) rsum[r * 3 + o] = part[rs][o];
            }
        }
        __syncthreads();
        if ((w >> 2) == 1 && (lane & 3) == 0) {
#pragma unroll
            for (int rs = 0; rs < 4; rs++) {
                int r = wm + (rs >> 1) * 16 + (rs & 1) * 8 + mrow;
#pragma unroll
                for (int o = 0; o < 3; o++) rsum[r * 3 + o] += part[rs][o];
            }
        }
        __syncthreads();
        float* scr = (float*)C1;
        for (int i = t; i < 384; i += 256) {
            int r = i / 3, o = i % 3;
            scr[((size_t)(row0 + r) * 2 + cblk) * 3 + o] = rsum[i];
        }
        return;
    }
#pragma unroll
    for (int mt = 0; mt < 2; mt++)
#pragma unroll
        for (int nt = 0; nt < 8; nt++) {
            int r = row0 + wm + mt * 16 + mrow;
            int cc = n0cta + wn + nt * 8 + ncol;
            if (EPI == 0) {
                uint32_t oh, om;
                silu_split2(acc[mt][nt][0], acc[mt][nt][1], &oh, &om);
                *(uint32_t*)((__half*)C1 + (size_t)r * HDIM + cc) = oh;
                *(uint32_t*)((__half*)C2 + (size_t)r * HDIM + cc) = om;
                silu_split2(acc[mt][nt][2], acc[mt][nt][3], &oh, &om);
                *(uint32_t*)((__half*)C1 + (size_t)(r + 8) * HDIM + cc) = oh;
                *(uint32_t*)((__half*)C2 + (size_t)(r + 8) * HDIM + cc) = om;
            } else {
                *(float2*)((float*)C1 + (size_t)r * HDIM + cc) =
                    make_float2(acc[mt][nt][0], acc[mt][nt][1]);
                *(float2*)((float*)C1 + (size_t)(r + 8) * HDIM + cc) =
                    make_float2(acc[mt][nt][2], acc[mt][nt][3]);
            }
        }
}

template <int EPI, int NC>
__global__ void __launch_bounds__(256, 2) gemm_kernel(
    const __half* __restrict__ Ahi, const __half* __restrict__ Amid,
    const __half* __restrict__ Bw,
    int ld, void* __restrict__ C1, void* __restrict__ C2,
    const float* __restrict__ W3) {
    extern __shared__ char smem[];
    gemm_core<EPI, NC>(Ahi, Amid, Bw, ld, C1, C2, W3,
                       blockIdx.y * 128, blockIdx.x * 128, blockIdx.x, smem);
}

struct PG {
    int boff[5];
    size_t coff[5];
};
__global__ void __launch_bounds__(256, 2) pgemm_kernel(
    const __half* __restrict__ hH, const __half* __restrict__ hM,
    const __half* __restrict__ wW, float* __restrict__ P, PG pg) {
    extern __shared__ char smem[];
    int z = blockIdx.z;
    gemm_core<1, 2>(hH, hM, wW + pg.boff[z], 128,
                    P + pg.coff[z], nullptr, nullptr,
                    blockIdx.y * 128, blockIdx.x * 128, blockIdx.x, smem);
}

__global__ void prep_h_kernel(const float* __restrict__ h,
                              __half* __restrict__ hi, __half* __restrict__ mid) {
    size_t idx = (size_t)blockIdx.x * 256 + threadIdx.x;
    int row = (int)(idx >> 7);
    float v = (row < 20000) ? h[idx] : 0.0f;
    __half hh = __float2half_rn(v);
    hi[idx] = hh;
    mid[idx] = __float2half_rn(v - __half2float(hh));
}

struct WS {
    const float* src[9];
    int KP[9], off[9];
};
__global__ void prep_w_kernel(WS S, __half* __restrict__ w) {
    int z = blockIdx.z;
    int KP = S.KP[z];
    if (blockIdx.x >= KP) return;
    int idx = blockIdx.x * 256 + threadIdx.x;
    int n = idx / KP, k = idx % KP;
    w[S.off[z] + idx] = __float2half_rn(S.src[z][(size_t)k * HDIM + n]);
}

__global__ void table_kernel(const float* __restrict__ eW0, const float* __restrict__ tW0,
                             const float* __restrict__ mu) {
    __shared__ float Wsm[100 * 64];
    __shared__ float rbf[32 * 100];
    int z = blockIdx.z, cb = blockIdx.y, r0 = blockIdx.x * 32;
    const float* Wsrc = ((z == 0) ? eW0 + 65536 : ((z == 1) ? tW0 + 98304 : tW0 + 123904))
                        + cb * 64;
    float* Tout = g_T + (size_t)z * TOFF + cb * 64;
    int t = threadIdx.x;
    for (int i = t; i < 6400; i += 256) {
        int k = i >> 6, c = i & 63;
        Wsm[i] = Wsrc[k * 256 + c];
    }
    for (int i = t; i < 3200; i += 256) {
        int rr = i / 100, k = i % 100;
        float r = (float)(r0 + rr) * (10.0f / (float)TABN);
        float d = __ldg(mu + k) - r;
        rbf[i] = expf(-10.0f * d * d);
    }
    __syncthreads();
    int col = t & 63, rl = t >> 6;
    float acc[8];
#pragma unroll
    for (int p = 0; p < 8; p++) acc[p] = 0.0f;
#pragma unroll 4
    for (int k = 0; k < 100; k++) {
        float wv = Wsm[k * 64 + col];
#pragma unroll
        for (int p = 0; p < 8; p++)
            acc[p] = fmaf(rbf[(rl + p * 4) * 100 + k], wv, acc[p]);
    }
#pragma unroll
    for (int p = 0; p < 8; p++) {
        int row = r0 + rl + p * 4;
        if (row <= TABN) Tout[(size_t)row * 256 + col] = acc[p];
    }
}

template <int MODE>
__global__ void __launch_bounds__(256) l0g_kernel(
    const float* __restrict__ rA, const float* __restrict__ rB,
    const float* __restrict__ cosv, const float* __restrict__ sinv,
    const int* __restrict__ iA, const int* __restrict__ iB, const int* __restrict__ iC,
    const float* __restrict__ Ta, const float* __restrict__ Tb,
    const float* __restrict__ Wcs,
    const float* __restrict__ Pa, const float* __restrict__ Pb, const float* __restrict__ Pc,
    __half* __restrict__ Chi, __half* __restrict__ Cmid) {
    int w = threadIdx.x >> 5, lane = threadIdx.x & 31;
    int row = blockIdx.x * 8 + w;

    float ua = rA[row] * ((float)TABN / 10.0f);
    int ia = min((int)ua, TABN - 1);
    float fa = ua - (float)ia;
    const float4* t0 = (const float4*)(Ta + (size_t)ia * 256);
    const float4* pa = (const float4*)(Pa + (size_t)iA[row] * HDIM);
    const float4* pb = (const float4*)(Pb + (size_t)iB[row] * HDIM);

    const float4* u0 = nullptr;
    const float4* pc = nullptr;
    float fb = 0.0f, cv = 0.0f, sv = 0.0f;
    if (MODE) {
        float ub = rB[row] * ((float)TABN / 10.0f);
        int ib = min((int)ub, TABN - 1);
        fb = ub - (float)ib;
        u0 = (const float4*)(Tb + (size_t)ib * 256);
        pc = (const float4*)(Pc + (size_t)iC[row] * HDIM);
        cv = cosv[row];
        sv = sinv[row];
    }

#pragma unroll
    for (int g = 0; g < 2; g++) {
        int c4 = lane + g * 32;
        float4 a0 = t0[c4], a1 = t0[c4 + 64];
        float4 A = pa[c4], B = pb[c4];
        float v[4];
        v[0] = a0.x + fa * (a1.x - a0.x) + A.x + B.x;
        v[1] = a0.y + fa * (a1.y - a0.y) + A.y + B.y;
        v[2] = a0.z + fa * (a1.z - a0.z) + A.z + B.z;
        v[3] = a0.w + fa * (a1.w - a0.w) + A.w + B.w;
        if (MODE) {
            float4 b0 = u0[c4], b1 = u0[c4 + 64];
            float4 C = pc[c4];
            float4 wc = ((const float4*)Wcs)[c4];
            float4 ws = ((const float4*)(Wcs + 256))[c4];
            v[0] += b0.x + fb * (b1.x - b0.x) + C.x + cv * wc.x + sv * ws.x;
            v[1] += b0.y + fb * (b1.y - b0.y) + C.y + cv * wc.y + sv * ws.y;
            v[2] += b0.z + fb * (b1.z - b0.z) + C.z + cv * wc.z + sv * ws.z;
            v[3] += b0.w + fb * (b1.w - b0.w) + C.w + cv * wc.w + sv * ws.w;
        }
        uint2 oh, om;
        silu_split2(v[0], v[1], &oh.x, &om.x);
        silu_split2(v[2], v[3], &oh.y, &om.y);
        *(uint2*)(Chi + (size_t)row * HDIM + c4 * 4) = oh;
        *(uint2*)(Cmid + (size_t)row * HDIM + c4 * 4) = om;
    }
}

__global__ void sum_kernel(const float* __restrict__ scr, const float* __restrict__ b3,
                           float* __restrict__ out, int n3) {
    int i = blockIdx.x * 256 + threadIdx.x;
    if (i >= n3) return;
    int row = i / 3, o = i % 3;
    out[i] = scr[row * 6 + o] + scr[row * 6 + 3 + o] + b3[o];
}

extern "C" void kernel_launch(void* const* d_in, const int* in_sizes, int n_in,
                              void* d_out, int out_size) {
    const float* h = (const float*)d_in[0];
    const int* src = (const int*)d_in[1];
    const int* dst = (const int*)d_in[2];
    const float* enorm = (const float*)d_in[3];
    const int* tsrc = (const int*)d_in[4];
    const int* tdi = (const int*)d_in[5];
    const int* tdj = (const int*)d_in[6];
    const float* nij = (const float*)d_in[7];
    const float* nik = (const float*)d_in[8];
    const float* cosv = (const float*)d_in[9];
    const float* sinv = (const float*)d_in[10];
    const float* mu = (const float*)d_in[11];
    const float* eW0 = (const float*)d_in[12];
    const float* eW1 = (const float*)d_in[13];
    const float* eW2 = (const float*)d_in[14];
    const float* eW3 = (const float*)d_in[15];
    const float* eb3 = (const float*)d_in[16];
    const float* tW0 = (const float*)d_in[17];
    const float* tW1 = (const float*)d_in[18];
    const float* tW2 = (const float*)d_in[19];
    const float* tW3 = (const float*)d_in[20];
    const float* tb3 = (const float*)d_in[21];
    float* out = (float*)d_out;

    __half *xH, *xM, *yH, *yM, *hH, *hM, *wW;
    float *P, *T, *scr;
    cudaGetSymbolAddress((void**)&xH, g_x_hi);
    cudaGetSymbolAddress((void**)&xM, g_x_mid);
    cudaGetSymbolAddress((void**)&yH, g_y_hi);
    cudaGetSymbolAddress((void**)&yM, g_y_mid);
    cudaGetSymbolAddress((void**)&hH, g_h_hi);
    cudaGetSymbolAddress((void**)&hM, g_h_mid);
    cudaGetSymbolAddress((void**)&wW, g_w);
    cudaGetSymbolAddress((void**)&P, g_P);
    cudaGetSymbolAddress((void**)&T, g_T);
    cudaGetSymbolAddress((void**)&scr, g_scr);

    cudaFuncSetAttribute((const void*)gemm_kernel<0, 4>,
                         cudaFuncAttributeMaxDynamicSharedMemorySize, SMEM_GEMM);
    cudaFuncSetAttribute((const void*)gemm_kernel<2, 4>,
                         cudaFuncAttributeMaxDynamicSharedMemorySize, SMEM_GEMM);
    cudaFuncSetAttribute((const void*)pgemm_kernel,
                         cudaFuncAttributeMaxDynamicSharedMemorySize, SMEM_GEMM);

    WS S;
    const float* srcs[9] = {eW0, eW0 + 32768, eW1, eW2, tW0, tW0 + 32768, tW0 + 65536, tW1, tW2};
    int KPs[9] = {128, 128, 256, 256, 128, 128, 128, 256, 256};
    int offs[9] = {E0A, E0B, E1, E2, T0A, T0B, T0C, T1, T2};
    for (int i = 0; i < 9; i++) { S.src[i] = srcs[i]; S.KP[i] = KPs[i]; S.off[i] = offs[i]; }
    prep_w_kernel<<<dim3(256, 1, 9), 256>>>(S, wW);
    prep_h_kernel<<<(NPAD * FDIM) / 256, 256>>>(h, hH, hM);
    table_kernel<<<dim3((TROWS + 31) / 32, 4, 3), 256>>>(eW0, tW0, mu);
    PG pg;
    int boffs[5] = {E0A, E0B, T0A, T0B, T0C};
    for (int i = 0; i < 5; i++) { pg.boff[i] = boffs[i]; pg.coff[i] = (size_t)i * PSZ; }
    pgemm_kernel<<<dim3(2, NPAD / 128, 5), 256, SMEM_GEMM>>>(hH, hM, wW, P, pg);

    float *Pea = P, *Peb = P + PSZ, *Pta = P + 2 * PSZ, *Ptb = P + 3 * PSZ, *Ptc = P + 4 * PSZ;
    dim3 ge(2, E_EDGES / 128), gt(2, T_TRIP / 128);
    l0g_kernel<0><<<E_EDGES / 8, 256>>>(enorm, nullptr, nullptr, nullptr,
                                        src, dst, nullptr, T, nullptr, nullptr,
                                        Pea, Peb, nullptr, xH, xM);
    gemm_kernel<0, 4><<<ge, 256, SMEM_GEMM>>>(xH, xM, wW + E1, 256, yH, yM, nullptr);
    gemm_kernel<2, 4><<<ge, 256, SMEM_GEMM>>>(yH, yM, wW + E2, 256, scr, nullptr, eW3);
    sum_kernel<<<(E_EDGES * 3 + 255) / 256, 256>>>(scr, eb3, out, E_EDGES * 3);
    l0g_kernel<1><<<T_TRIP / 8, 256>>>(nij, nik, cosv, sinv,
                                       tsrc, tdi, tdj, T + TOFF, T + 2 * TOFF,
                                       tW0 + 149504, Pta, Ptb, Ptc, xH, xM);
    gemm_kernel<0, 4><<<gt, 256, SMEM_GEMM>>>(xH, xM, wW + T1, 256, yH, yM, nullptr);
    gemm_kernel<2, 4><<<gt, 256, SMEM_GEMM>>>(yH, yM, wW + T2, 256, scr, nullptr, tW3);
    sum_kernel<<<(T_TRIP * 3 + 255) / 256, 256>>>(scr, tb3, out + (size_t)E_EDGES * 3,
                                                  T_TRIP * 3);
}